// round 16
// baseline (speedup 1.0000x reference)
#include <cuda_runtime.h>
#include <cuda_fp16.h>
#include <math.h>
#include <stdint.h>

// ---------------------------------------------------------------------------
// SpatialAttentionConv, R16: fp16 2-term split-GEMMs (A = Ah+Al fp16 exact to
// ~2^-22; W single fp16 -> only W-quant error ~1.4e-4). MMA count -33% vs the
// bf16 3-term scheme. All preps fused into one block-partitioned kernel so
// out_gemm lands in ncu's profile slot (launch #4).
//
//   GEMM1: g_qkv(N x 384) = X @ ipw^T + ipb          (secs 0..2 in one CTA)
//   attn : per-face 8-neighbor masked ONLINE softmax, fp32
//   GEMM2: out = O @ W2^T + X @ cw0^T + b2,  W2 = Cw1@Wo, b2 = Cw1@bo + cb
// ---------------------------------------------------------------------------

#define MAXN 200064

static __device__ float g_qkv[(size_t)MAXN * 384];
static __device__ float g_o[(size_t)MAXN * 128];
static __device__ float g_b2[128];
static __device__ uint2 g_bfm[8 * 64 * 32];   // fp16 B frags: [ks][ntile][lane]
                                              // ntile 0..47: ipw, 48..63: cw0
static __device__ uint2 g_bf2[8 * 16 * 32];   // fp16 W2 frags
static __device__ int g_is64;

// ------------------------------ helpers ------------------------------------
__device__ __forceinline__ uint32_t smem_u32(const void* p) {
    uint32_t a;
    asm("{ .reg .u64 t; cvta.to.shared.u64 t, %1; cvt.u32.u64 %0, t; }" : "=r"(a) : "l"(p));
    return a;
}
__device__ __forceinline__ uint32_t pk2h(float a, float b) {
    __half2 t = __floats2half2_rn(a, b);
    return *reinterpret_cast<uint32_t*>(&t);
}
__device__ __forceinline__ float hfl(float v) {   // v - fp16_round(v)
    return v - __half2float(__float2half_rn(v));
}

#define LDMATRIX_X4(r0, r1, r2, r3, addr) \
    asm volatile("ldmatrix.sync.aligned.m8n8.x4.shared.b16 {%0,%1,%2,%3}, [%4];" \
                 : "=r"(r0), "=r"(r1), "=r"(r2), "=r"(r3) : "r"(addr))

#define MMA16816(d, a, b0, b1) \
    asm volatile("mma.sync.aligned.m16n8k16.row.col.f32.f16.f16.f32 " \
                 "{%0,%1,%2,%3}, {%4,%5,%6,%7}, {%8,%9}, {%0,%1,%2,%3};" \
                 : "+f"((d)[0]), "+f"((d)[1]), "+f"((d)[2]), "+f"((d)[3]) \
                 : "r"((a)[0]), "r"((a)[1]), "r"((a)[2]), "r"((a)[3]), \
                   "r"(b0), "r"(b1))

#define SMEM_BYTES 65536            // hi tile 32KB + lo tile 32KB

// --------------------- fused prep (one kernel, 81 blocks) ------------------
// blocks 0..63 : GEMM1 B fragments (ipw secs 0..2 + cw0 tap as ntiles 48..63)
// blocks 64..79: W2 = Cw1 @ Wo fragments, computed directly; block 64 also b2
// block  80    : int64-vs-int32 index detection
__global__ void prep_all(const float* __restrict__ ipw,
                         const float* __restrict__ cw,
                         const float* __restrict__ opw,
                         const float* __restrict__ opb,
                         const float* __restrict__ cb,
                         const int* __restrict__ nbr32) {
    const int b = blockIdx.x, t = threadIdx.x;
    if (b < 64) {
        // B fragments in mma register layout (m16n8k16.row.col):
        //   reg0: B[k=(l%4)*2+{0,1}, n=l/4]; reg1: B[k=(l%4)*2+8+{0,1}, n=l/4]
        int idx = b * 256 + t;                       // 16384
        int lane = idx & 31, nt = (idx >> 5) & 63, ks = idx >> 11;
        int n = nt * 8 + (lane >> 2);
        int k0 = ks * 16 + (lane & 3) * 2;
        float v[4];
        #pragma unroll
        for (int j = 0; j < 4; ++j) {
            int k = k0 + (j >> 1) * 8 + (j & 1);
            v[j] = (n < 384) ? ipw[n * 128 + k] : cw[((n - 384) * 128 + k) * 2];
        }
        g_bfm[idx] = make_uint2(pk2h(v[0], v[1]), pk2h(v[2], v[3]));
    } else if (b < 80) {
        int idx = (b - 64) * 256 + t;                // 4096
        int lane = idx & 31, nt = (idx >> 5) & 15, ks = idx >> 9;
        int n = nt * 8 + (lane >> 2);
        int k0 = ks * 16 + (lane & 3) * 2;
        float v[4];
        #pragma unroll
        for (int j = 0; j < 4; ++j) {
            int k = k0 + (j >> 1) * 8 + (j & 1);
            float s = 0.f;
            #pragma unroll 4
            for (int m = 0; m < 128; ++m)
                s += cw[(n * 128 + m) * 2 + 1] * opw[m * 128 + k];
            v[j] = s;
        }
        g_bf2[idx] = make_uint2(pk2h(v[0], v[1]), pk2h(v[2], v[3]));
        if (idx < 128) {                             // b2 = Cw1 @ bo + cb
            float s = 0.f;
            for (int m = 0; m < 128; ++m)
                s += cw[(idx * 128 + m) * 2 + 1] * opb[m];
            g_b2[idx] = s + cb[idx];
        }
    } else {
        if (t == 0) {
            int any = 0;
            #pragma unroll 1
            for (int j = 1; j < 128; ++j) any |= nbr32[2 * j + 1];
            g_is64 = (any == 0) ? 1 : 0;
        }
    }
}

// ---------------------------------------------------------------------------
// Shared A tile: 128 rows x 128 fp16 (256B/row), hi at 0, lo at 32KB.
// 16B chunk (r, c) at r*256 + (c ^ (r & 7))*16 -> conflict-free ldmatrix.
// A = hi + lo represents the fp32 input to ~2^-22 (11+11 mantissa bits).
// ---------------------------------------------------------------------------
__device__ __forceinline__ void fill_tile(const float* __restrict__ src,
                                          char* smem, int m0, int M, int tid) {
    #pragma unroll 1
    for (int i = tid; i < 2048; i += 256) {
        int r = i >> 4, c = i & 15;
        float4 v0 = make_float4(0.f, 0.f, 0.f, 0.f), v1 = v0;
        if (m0 + r < M) {
            const float* p = src + (size_t)(m0 + r) * 128 + c * 8;
            v0 = *(const float4*)p;
            v1 = *(const float4*)(p + 4);
        }
        uint4 hi, lo;
        hi.x = pk2h(v0.x, v0.y); hi.y = pk2h(v0.z, v0.w);
        hi.z = pk2h(v1.x, v1.y); hi.w = pk2h(v1.z, v1.w);
        lo.x = pk2h(hfl(v0.x), hfl(v0.y)); lo.y = pk2h(hfl(v0.z), hfl(v0.w));
        lo.z = pk2h(hfl(v1.x), hfl(v1.y)); lo.w = pk2h(hfl(v1.z), hfl(v1.w));
        uint32_t off = (uint32_t)(r * 256 + ((c ^ (r & 7)) << 4));
        *(uint4*)(smem + off) = hi;
        *(uint4*)(smem + 32768 + off) = lo;
    }
}

// MMA pass, 2m x 4n layout, fp16 2-term: per (m-frag, n-frag) only
//   acc += Ah @ W ; acc += Al @ W      (32 MMAs per ks vs 48 in 3-term)
__device__ __forceinline__ void mma_pass(uint32_t sb, const uint2* __restrict__ bfr,
                                         int ntb, int nstride, int lane,
                                         int wm2, float acc[4][4][4]) {
    const int lr = lane & 15, lc = lane >> 4, ls = lane & 7;
    #pragma unroll 1
    for (int ks = 0; ks < 8; ++ks) {
        uint32_t ch = (uint32_t)((((ks * 2 + lc) ^ ls)) << 4);
        uint2 b[4];
        #pragma unroll
        for (int nf = 0; nf < 4; ++nf)
            b[nf] = __ldg(&bfr[(ks * nstride + ntb + nf) * 32 + lane]);
        uint32_t ah[4][4], al[4][4];
        #pragma unroll
        for (int m4 = 0; m4 < 4; ++m4) {
            uint32_t ao = (uint32_t)((wm2 * 64 + m4 * 16 + lr) * 256);
            LDMATRIX_X4(ah[m4][0], ah[m4][1], ah[m4][2], ah[m4][3],
                        sb + ao + ch);
            LDMATRIX_X4(al[m4][0], al[m4][1], al[m4][2], al[m4][3],
                        sb + 32768 + ao + ch);
        }
        #pragma unroll
        for (int m4 = 0; m4 < 4; ++m4) {
            #pragma unroll
            for (int nf = 0; nf < 4; ++nf) {
                MMA16816(acc[m4][nf], ah[m4], b[nf].x, b[nf].y);
                MMA16816(acc[m4][nf], al[m4], b[nf].x, b[nf].y);
            }
        }
    }
}

// -------------------- GEMM1: QKV, 3 sections per CTA -----------------------
__global__ void __launch_bounds__(256, 2)
mega_gemm(const float* __restrict__ x, const float* __restrict__ ipb, int M) {
    extern __shared__ char smem[];
    const int tid = threadIdx.x;
    const int m0 = blockIdx.x * 128;
    const int w = tid >> 5, lane = tid & 31;
    const int wm2 = w & 1, wn4 = w >> 1;

    fill_tile(x, smem, m0, M, tid);
    __syncthreads();

    const uint32_t sb = smem_u32(smem);
    const int qrow = lane >> 2, qcol = (lane & 3) * 2;

    #pragma unroll 1
    for (int sec = 0; sec < 3; ++sec) {
        float acc[4][4][4];
        #pragma unroll
        for (int mf = 0; mf < 4; ++mf)
            #pragma unroll
            for (int nf = 0; nf < 4; ++nf)
                #pragma unroll
                for (int q = 0; q < 4; ++q) acc[mf][nf][q] = 0.f;

        mma_pass(sb, g_bfm, sec * 16 + wn4 * 4, 64, lane, wm2, acc);

        // Direct fragment epilogue with bias (quad spans 32B -> coalesced).
        float bv[4][2];
        #pragma unroll
        for (int nf = 0; nf < 4; ++nf) {
            int col = sec * 128 + wn4 * 32 + nf * 8 + qcol;
            bv[nf][0] = __ldg(ipb + col);
            bv[nf][1] = __ldg(ipb + col + 1);
        }
        #pragma unroll
        for (int mf = 0; mf < 4; ++mf) {
            int r0 = m0 + wm2 * 64 + mf * 16 + qrow;
            #pragma unroll
            for (int nf = 0; nf < 4; ++nf) {
                int col = sec * 128 + wn4 * 32 + nf * 8 + qcol;
                if (r0 < M)
                    *(float2*)(g_qkv + (size_t)r0 * 384 + col) =
                        make_float2(acc[mf][nf][0] + bv[nf][0],
                                    acc[mf][nf][1] + bv[nf][1]);
                if (r0 + 8 < M)
                    *(float2*)(g_qkv + (size_t)(r0 + 8) * 384 + col) =
                        make_float2(acc[mf][nf][2] + bv[nf][0],
                                    acc[mf][nf][3] + bv[nf][1]);
            }
        }
    }
}

// -------------------- GEMM2: out = O@W2^T + X@cw0^T + b2 -------------------
__global__ void __launch_bounds__(256, 2)
out_gemm(const float* __restrict__ x, float* __restrict__ out, int M) {
    extern __shared__ char smem[];
    const int tid = threadIdx.x;
    const int m0 = blockIdx.x * 128;
    const int w = tid >> 5, lane = tid & 31;
    const int wm2 = w & 1, wn4 = w >> 1;

    float acc[4][4][4];
    #pragma unroll
    for (int mf = 0; mf < 4; ++mf)
        #pragma unroll
        for (int nf = 0; nf < 4; ++nf)
            #pragma unroll
            for (int q = 0; q < 4; ++q) acc[mf][nf][q] = 0.f;

    // Pass 1: O @ W2^T
    fill_tile(g_o, smem, m0, M, tid);
    __syncthreads();
    mma_pass(smem_u32(smem), g_bf2, wn4 * 4, 16, lane, wm2, acc);
    __syncthreads();

    // Pass 2: X @ cw0^T (cw0 = ntiles 48..63 of g_bfm)
    fill_tile(x, smem, m0, M, tid);
    __syncthreads();
    mma_pass(smem_u32(smem), g_bfm, 48 + wn4 * 4, 64, lane, wm2, acc);

    // Direct fragment epilogue with bias.
    const int qrow = lane >> 2, qcol = (lane & 3) * 2;
    float bv[4][2];
    #pragma unroll
    for (int nf = 0; nf < 4; ++nf) {
        int col = wn4 * 32 + nf * 8 + qcol;
        bv[nf][0] = __ldg(g_b2 + col);
        bv[nf][1] = __ldg(g_b2 + col + 1);
    }
    #pragma unroll
    for (int mf = 0; mf < 4; ++mf) {
        int r0 = m0 + wm2 * 64 + mf * 16 + qrow;
        #pragma unroll
        for (int nf = 0; nf < 4; ++nf) {
            int col = wn4 * 32 + nf * 8 + qcol;
            if (r0 < M)
                *(float2*)(out + (size_t)r0 * 128 + col) =
                    make_float2(acc[mf][nf][0] + bv[nf][0],
                                acc[mf][nf][1] + bv[nf][1]);
            if (r0 + 8 < M)
                *(float2*)(out + (size_t)(r0 + 8) * 128 + col) =
                    make_float2(acc[mf][nf][2] + bv[nf][0],
                                acc[mf][nf][3] + bv[nf][1]);
        }
    }
}

// ------------------ attention: streaming (online) softmax -------------------
__global__ void __launch_bounds__(256)
attn_kernel(const void* __restrict__ nbr, int N) {
    const int lane = threadIdx.x & 31;
    const int face = blockIdx.x * (blockDim.x >> 5) + (threadIdx.x >> 5);
    if (face >= N) return;

    const float* __restrict__ qkv = g_qkv;
    const float4 q = *(const float4*)&qkv[(size_t)face * 384 + lane * 4];

    int myj = 0;
    if (lane < 8) {
        if (g_is64) myj = (int)((const long long*)nbr)[(size_t)face * 9 + 1 + lane];
        else        myj = ((const int*)nbr)[(size_t)face * 9 + 1 + lane];
    }

    const float scale = 0.17677669529663687f;  // 1/sqrt(32)
    float m = -INFINITY, den = 0.f;
    float4 oacc = make_float4(0.f, 0.f, 0.f, 0.f);

    #pragma unroll
    for (int kk = 0; kk < 8; ++kk) {
        int j = __shfl_sync(0xffffffffu, myj, kk);
        if (j < N) {
            const float* base = &qkv[(size_t)j * 384 + 128 + lane * 4];
            float4 kf = *(const float4*)base;
            float4 v  = *(const float4*)(base + 128);
            float p = q.x * kf.x + q.y * kf.y + q.z * kf.z + q.w * kf.w;
            p += __shfl_xor_sync(0xffffffffu, p, 1);
            p += __shfl_xor_sync(0xffffffffu, p, 2);
            p += __shfl_xor_sync(0xffffffffu, p, 4);   // 8-lane head reduce
            float s = p * scale;
            float nm = fmaxf(m, s);
            float corr = __expf(m - nm);               // 0 on first hit
            float e = __expf(s - nm);
            den = den * corr + e;
            oacc.x = oacc.x * corr + e * v.x;
            oacc.y = oacc.y * corr + e * v.y;
            oacc.z = oacc.z * corr + e * v.z;
            oacc.w = oacc.w * corr + e * v.w;
            m = nm;
        }
    }

    const float inv = 1.0f / den;
    oacc.x *= inv; oacc.y *= inv; oacc.z *= inv; oacc.w *= inv;

    *(float4*)&g_o[(size_t)face * 128 + lane * 4] = oacc;
}

// ------------------------------ launch -------------------------------------
// Four launches; out_gemm is #4 -> lands in ncu's fixed profile window.
extern "C" void kernel_launch(void* const* d_in, const int* in_sizes, int n_in,
                              void* d_out, int out_size) {
    const float* x   = (const float*)d_in[0];
    const void*  nbr = d_in[1];
    const float* ipw = (const float*)d_in[4];
    const float* ipb = (const float*)d_in[5];
    const float* opw = (const float*)d_in[6];
    const float* opb = (const float*)d_in[7];
    const float* cw  = (const float*)d_in[8];
    const float* cb  = (const float*)d_in[9];
    const int N = in_sizes[0] / 128;
    float* out = (float*)d_out;

    cudaFuncSetAttribute(mega_gemm, cudaFuncAttributeMaxDynamicSharedMemorySize, SMEM_BYTES);
    cudaFuncSetAttribute(out_gemm, cudaFuncAttributeMaxDynamicSharedMemorySize, SMEM_BYTES);

    const int tiles = (N + 127) / 128;

    prep_all<<<81, 256>>>(ipw, cw, opw, opb, cb, (const int*)nbr);   // 1
    mega_gemm<<<tiles, 256, SMEM_BYTES>>>(x, ipb, N);                // 2
    attn_kernel<<<(N + 7) / 8, 256>>>(nbr, N);                       // 3
    out_gemm<<<tiles, 256, SMEM_BYTES>>>(x, out, N);                 // 4 <- ncu
}

// round 17
// speedup vs baseline: 1.3332x; 1.3332x over previous
#include <cuda_runtime.h>
#include <cuda_bf16.h>
#include <cuda_fp16.h>
#include <math.h>
#include <stdint.h>

// ---------------------------------------------------------------------------
// SpatialAttentionConv, R17: R15 bf16 3-term GEMMs (reverted from the fp16
// 2-term regression) + compact attention operands: Q,K in a 256-float row
// (g_qk), V quantized to fp16 (g_vh). Gather bytes/neighbor 1024 -> 768.
//
//   GEMM1: g_qk(N x 256) = X @ ipw[0:256]^T + b, g_vh(N x 128 fp16) = V
//   attn : per-face 8-neighbor masked ONLINE softmax, fp32 scores, fp16 V
//   GEMM2: out = O @ W2^T + X @ cw0^T + b2,  W2 = Cw1@Wo, b2 = Cw1@bo + cb
// Split trick: A = Ah + Al (bf16); A@W ~= Ah@Wh + Al@Wh + Ah@Wl (fp32 accum).
// ---------------------------------------------------------------------------

#define MAXN 200064

static __device__ float  g_qk[(size_t)MAXN * 256];
static __device__ __half g_vh[(size_t)MAXN * 128];
static __device__ float  g_o[(size_t)MAXN * 128];
static __device__ float  g_w2[128 * 128];
static __device__ float  g_b2[128];
static __device__ uint4  g_bfm[8 * 64 * 32];  // B frags: [ks][ntile 0..63][lane]
                                              // ntile 0..47: ipw, 48..63: cw0
static __device__ uint4  g_bf2[8 * 16 * 32];  // W2 frags
static __device__ int    g_is64;

// ------------------------------ helpers ------------------------------------
__device__ __forceinline__ uint32_t smem_u32(const void* p) {
    uint32_t a;
    asm("{ .reg .u64 t; cvta.to.shared.u64 t, %1; cvt.u32.u64 %0, t; }" : "=r"(a) : "l"(p));
    return a;
}
__device__ __forceinline__ uint32_t pk2(float a, float b) {
    __nv_bfloat162 t = __floats2bfloat162_rn(a, b);
    return *reinterpret_cast<uint32_t*>(&t);
}
__device__ __forceinline__ float bfl(float v) {   // v - bf16_round(v)
    return v - __bfloat162float(__float2bfloat16(v));
}

#define LDMATRIX_X4(r0, r1, r2, r3, addr) \
    asm volatile("ldmatrix.sync.aligned.m8n8.x4.shared.b16 {%0,%1,%2,%3}, [%4];" \
                 : "=r"(r0), "=r"(r1), "=r"(r2), "=r"(r3) : "r"(addr))

#define MMA16816(d, a, b0, b1) \
    asm volatile("mma.sync.aligned.m16n8k16.row.col.f32.bf16.bf16.f32 " \
                 "{%0,%1,%2,%3}, {%4,%5,%6,%7}, {%8,%9}, {%0,%1,%2,%3};" \
                 : "+f"((d)[0]), "+f"((d)[1]), "+f"((d)[2]), "+f"((d)[3]) \
                 : "r"((a)[0]), "r"((a)[1]), "r"((a)[2]), "r"((a)[3]), \
                   "r"(b0), "r"(b1))

#define SMEM_BYTES 65536            // hi tile 32KB + lo tile 32KB

// ------------------------------ small preps --------------------------------
__global__ void detect_kernel(const int* __restrict__ nbr32) {
    if (threadIdx.x == 0) {
        int any = 0;
        #pragma unroll 1
        for (int j = 1; j < 128; ++j) any |= nbr32[2 * j + 1];
        g_is64 = (any == 0) ? 1 : 0;
    }
}

__global__ void prep_w2_kernel(const float* __restrict__ conv_w,
                               const float* __restrict__ out_proj_w,
                               const float* __restrict__ out_proj_b,
                               const float* __restrict__ conv_b) {
    int n = blockIdx.x, i = threadIdx.x;
    float s = 0.f;
    #pragma unroll 4
    for (int m = 0; m < 128; ++m)
        s += conv_w[(n * 128 + m) * 2 + 1] * out_proj_w[m * 128 + i];
    g_w2[n * 128 + i] = s;
    if (i == 0) {
        float b = 0.f;
        for (int m = 0; m < 128; ++m)
            b += conv_w[(n * 128 + m) * 2 + 1] * out_proj_b[m];
        g_b2[n] = b + conv_b[n];
    }
}

// B fragments in mma register layout (m16n8k16.row.col):
//   reg0: B[k=(l%4)*2+{0,1},   n=l/4];  reg1: B[k=(l%4)*2+8+{0,1}, n=l/4]
// uint4 = {bh_reg0, bh_reg1, bl_reg0, bl_reg1}.
__global__ void prep_frag_mega(const float* __restrict__ ipw,
                               const float* __restrict__ cw) {
    int idx = blockIdx.x * blockDim.x + threadIdx.x;     // 16384
    int lane = idx & 31, t = (idx >> 5) & 63, ks = idx >> 11;
    int n = t * 8 + (lane >> 2);
    int k0 = ks * 16 + (lane & 3) * 2;
    float v[4];
    #pragma unroll
    for (int j = 0; j < 4; ++j) {
        int k = k0 + (j >> 1) * 8 + (j & 1);
        v[j] = (n < 384) ? ipw[n * 128 + k] : cw[((n - 384) * 128 + k) * 2];
    }
    uint4 o;
    o.x = pk2(v[0], v[1]);
    o.y = pk2(v[2], v[3]);
    o.z = pk2(bfl(v[0]), bfl(v[1]));
    o.w = pk2(bfl(v[2]), bfl(v[3]));
    g_bfm[idx] = o;
}

__global__ void prep_frag_w2() {
    int idx = blockIdx.x * blockDim.x + threadIdx.x;     // 4096
    int lane = idx & 31, t = (idx >> 5) & 15, ks = idx >> 9;
    int n = t * 8 + (lane >> 2);
    int k0 = ks * 16 + (lane & 3) * 2;
    float v[4];
    #pragma unroll
    for (int j = 0; j < 4; ++j)
        v[j] = g_w2[n * 128 + k0 + (j >> 1) * 8 + (j & 1)];
    uint4 o;
    o.x = pk2(v[0], v[1]);
    o.y = pk2(v[2], v[3]);
    o.z = pk2(bfl(v[0]), bfl(v[1]));
    o.w = pk2(bfl(v[2]), bfl(v[3]));
    g_bf2[idx] = o;
}

// ---------------------------------------------------------------------------
// Shared A tile: 128 rows x 128 bf16 (256B/row), hi at 0, lo at 32KB.
// 16B chunk (r, c) at r*256 + (c ^ (r & 7))*16 -> conflict-free ldmatrix.
// ---------------------------------------------------------------------------
__device__ __forceinline__ void fill_tile(const float* __restrict__ src,
                                          char* smem, int m0, int M, int tid) {
    #pragma unroll 1
    for (int i = tid; i < 2048; i += 256) {
        int r = i >> 4, c = i & 15;
        float4 v0 = make_float4(0.f, 0.f, 0.f, 0.f), v1 = v0;
        if (m0 + r < M) {
            const float* p = src + (size_t)(m0 + r) * 128 + c * 8;
            v0 = *(const float4*)p;
            v1 = *(const float4*)(p + 4);
        }
        uint4 hi, lo;
        hi.x = pk2(v0.x, v0.y); hi.y = pk2(v0.z, v0.w);
        hi.z = pk2(v1.x, v1.y); hi.w = pk2(v1.z, v1.w);
        lo.x = pk2(bfl(v0.x), bfl(v0.y)); lo.y = pk2(bfl(v0.z), bfl(v0.w));
        lo.z = pk2(bfl(v1.x), bfl(v1.y)); lo.w = pk2(bfl(v1.z), bfl(v1.w));
        uint32_t off = (uint32_t)(r * 256 + ((c ^ (r & 7)) << 4));
        *(uint4*)(smem + off) = hi;
        *(uint4*)(smem + 32768 + off) = lo;
    }
}

// MMA pass, 2m x 4n layout: warp w = (wm2 = w&1, wn4 = w>>1).
__device__ __forceinline__ void mma_pass(uint32_t sb, const uint4* __restrict__ bfr,
                                         int ntb, int nstride, int lane,
                                         int wm2, float acc[4][4][4]) {
    const int lr = lane & 15, lc = lane >> 4, ls = lane & 7;
    #pragma unroll 1
    for (int ks = 0; ks < 8; ++ks) {
        uint32_t ch = (uint32_t)((((ks * 2 + lc) ^ ls)) << 4);
        uint4 b[4];
        #pragma unroll
        for (int nf = 0; nf < 4; ++nf)
            b[nf] = __ldg(&bfr[(ks * nstride + ntb + nf) * 32 + lane]);
        uint32_t ah[4][4], al[4][4];
        #pragma unroll
        for (int m4 = 0; m4 < 4; ++m4) {
            uint32_t ao = (uint32_t)((wm2 * 64 + m4 * 16 + lr) * 256);
            LDMATRIX_X4(ah[m4][0], ah[m4][1], ah[m4][2], ah[m4][3],
                        sb + ao + ch);
            LDMATRIX_X4(al[m4][0], al[m4][1], al[m4][2], al[m4][3],
                        sb + 32768 + ao + ch);
        }
        #pragma unroll
        for (int m4 = 0; m4 < 4; ++m4) {
            #pragma unroll
            for (int nf = 0; nf < 4; ++nf) {
                MMA16816(acc[m4][nf], ah[m4], b[nf].x, b[nf].y);
                MMA16816(acc[m4][nf], al[m4], b[nf].x, b[nf].y);
                MMA16816(acc[m4][nf], ah[m4], b[nf].z, b[nf].w);
            }
        }
    }
}

// -------------------- GEMM1: QKV, 3 sections per CTA -----------------------
// Fill the X tile once; loop sections. Secs 0,1 (Q,K) -> g_qk fp32;
// sec 2 (V) -> g_vh fp16 only (fp32 V is never needed downstream).
__global__ void __launch_bounds__(256, 2)
mega_gemm(const float* __restrict__ x, const float* __restrict__ ipb, int M) {
    extern __shared__ char smem[];
    const int tid = threadIdx.x;
    const int m0 = blockIdx.x * 128;
    const int w = tid >> 5, lane = tid & 31;
    const int wm2 = w & 1, wn4 = w >> 1;

    fill_tile(x, smem, m0, M, tid);
    __syncthreads();

    const uint32_t sb = smem_u32(smem);
    const int qrow = lane >> 2, qcol = (lane & 3) * 2;

    #pragma unroll 1
    for (int sec = 0; sec < 3; ++sec) {
        float acc[4][4][4];
        #pragma unroll
        for (int mf = 0; mf < 4; ++mf)
            #pragma unroll
            for (int nf = 0; nf < 4; ++nf)
                #pragma unroll
                for (int q = 0; q < 4; ++q) acc[mf][nf][q] = 0.f;

        mma_pass(sb, g_bfm, sec * 16 + wn4 * 4, 64, lane, wm2, acc);

        // Direct fragment epilogue with bias (quad spans 32B -> coalesced).
        float bv[4][2];
        #pragma unroll
        for (int nf = 0; nf < 4; ++nf) {
            int col = sec * 128 + wn4 * 32 + nf * 8 + qcol;
            bv[nf][0] = __ldg(ipb + col);
            bv[nf][1] = __ldg(ipb + col + 1);
        }
        #pragma unroll
        for (int mf = 0; mf < 4; ++mf) {
            int r0 = m0 + wm2 * 64 + mf * 16 + qrow;
            #pragma unroll
            for (int nf = 0; nf < 4; ++nf) {
                int lcol = wn4 * 32 + nf * 8 + qcol;
                if (sec < 2) {
                    int col = sec * 128 + lcol;
                    if (r0 < M)
                        *(float2*)(g_qk + (size_t)r0 * 256 + col) =
                            make_float2(acc[mf][nf][0] + bv[nf][0],
                                        acc[mf][nf][1] + bv[nf][1]);
                    if (r0 + 8 < M)
                        *(float2*)(g_qk + (size_t)(r0 + 8) * 256 + col) =
                            make_float2(acc[mf][nf][2] + bv[nf][0],
                                        acc[mf][nf][3] + bv[nf][1]);
                } else {
                    if (r0 < M)
                        *(__half2*)(g_vh + (size_t)r0 * 128 + lcol) =
                            __floats2half2_rn(acc[mf][nf][0] + bv[nf][0],
                                              acc[mf][nf][1] + bv[nf][1]);
                    if (r0 + 8 < M)
                        *(__half2*)(g_vh + (size_t)(r0 + 8) * 128 + lcol) =
                            __floats2half2_rn(acc[mf][nf][2] + bv[nf][0],
                                              acc[mf][nf][3] + bv[nf][1]);
                }
            }
        }
    }
}

// -------------------- GEMM2: out = O@W2^T + X@cw0^T + b2 -------------------
__global__ void __launch_bounds__(256, 2)
out_gemm(const float* __restrict__ x, float* __restrict__ out, int M) {
    extern __shared__ char smem[];
    const int tid = threadIdx.x;
    const int m0 = blockIdx.x * 128;
    const int w = tid >> 5, lane = tid & 31;
    const int wm2 = w & 1, wn4 = w >> 1;

    float acc[4][4][4];
    #pragma unroll
    for (int mf = 0; mf < 4; ++mf)
        #pragma unroll
        for (int nf = 0; nf < 4; ++nf)
            #pragma unroll
            for (int q = 0; q < 4; ++q) acc[mf][nf][q] = 0.f;

    // Pass 1: O @ W2^T
    fill_tile(g_o, smem, m0, M, tid);
    __syncthreads();
    mma_pass(smem_u32(smem), g_bf2, wn4 * 4, 16, lane, wm2, acc);
    __syncthreads();

    // Pass 2: X @ cw0^T (cw0 = ntiles 48..63 of g_bfm)
    fill_tile(x, smem, m0, M, tid);
    __syncthreads();
    mma_pass(smem_u32(smem), g_bfm, 48 + wn4 * 4, 64, lane, wm2, acc);

    // Direct fragment epilogue with bias.
    const int qrow = lane >> 2, qcol = (lane & 3) * 2;
    float bv[4][2];
    #pragma unroll
    for (int nf = 0; nf < 4; ++nf) {
        int col = wn4 * 32 + nf * 8 + qcol;
        bv[nf][0] = __ldg(g_b2 + col);
        bv[nf][1] = __ldg(g_b2 + col + 1);
    }
    #pragma unroll
    for (int mf = 0; mf < 4; ++mf) {
        int r0 = m0 + wm2 * 64 + mf * 16 + qrow;
        #pragma unroll
        for (int nf = 0; nf < 4; ++nf) {
            int col = wn4 * 32 + nf * 8 + qcol;
            if (r0 < M)
                *(float2*)(out + (size_t)r0 * 128 + col) =
                    make_float2(acc[mf][nf][0] + bv[nf][0],
                                acc[mf][nf][1] + bv[nf][1]);
            if (r0 + 8 < M)
                *(float2*)(out + (size_t)(r0 + 8) * 128 + col) =
                    make_float2(acc[mf][nf][2] + bv[nf][0],
                                acc[mf][nf][3] + bv[nf][1]);
        }
    }
}

// ------------------ attention: streaming softmax, fp16 V --------------------
// Scores in exact fp32 (Q,K fp32 from g_qk); V gathered as fp16 (g_vh).
__global__ void __launch_bounds__(256)
attn_kernel(const void* __restrict__ nbr, int N) {
    const int lane = threadIdx.x & 31;
    const int face = blockIdx.x * (blockDim.x >> 5) + (threadIdx.x >> 5);
    if (face >= N) return;

    const float4 q = *(const float4*)&g_qk[(size_t)face * 256 + lane * 4];

    int myj = 0;
    if (lane < 8) {
        if (g_is64) myj = (int)((const long long*)nbr)[(size_t)face * 9 + 1 + lane];
        else        myj = ((const int*)nbr)[(size_t)face * 9 + 1 + lane];
    }

    const float scale = 0.17677669529663687f;  // 1/sqrt(32)
    float m = -INFINITY, den = 0.f;
    float4 oacc = make_float4(0.f, 0.f, 0.f, 0.f);

    #pragma unroll
    for (int kk = 0; kk < 8; ++kk) {
        int j = __shfl_sync(0xffffffffu, myj, kk);
        if (j < N) {
            float4 kf = *(const float4*)&g_qk[(size_t)j * 256 + 128 + lane * 4];
            uint2 vraw = *(const uint2*)(g_vh + (size_t)j * 128 + lane * 4);
            float2 va = __half22float2(*reinterpret_cast<__half2*>(&vraw.x));
            float2 vb = __half22float2(*reinterpret_cast<__half2*>(&vraw.y));
            float p = q.x * kf.x + q.y * kf.y + q.z * kf.z + q.w * kf.w;
            p += __shfl_xor_sync(0xffffffffu, p, 1);
            p += __shfl_xor_sync(0xffffffffu, p, 2);
            p += __shfl_xor_sync(0xffffffffu, p, 4);   // 8-lane head reduce
            float s = p * scale;
            float nm = fmaxf(m, s);
            float corr = __expf(m - nm);               // 0 on first hit
            float e = __expf(s - nm);
            den = den * corr + e;
            oacc.x = oacc.x * corr + e * va.x;
            oacc.y = oacc.y * corr + e * va.y;
            oacc.z = oacc.z * corr + e * vb.x;
            oacc.w = oacc.w * corr + e * vb.y;
            m = nm;
        }
    }

    const float inv = 1.0f / den;
    oacc.x *= inv; oacc.y *= inv; oacc.z *= inv; oacc.w *= inv;

    *(float4*)&g_o[(size_t)face * 128 + lane * 4] = oacc;
}

// ------------------------------ launch -------------------------------------
// attn_kernel in launch slot 4 (ncu's fixed profile window) to verify the
// fp16-V gather reduction.
extern "C" void kernel_launch(void* const* d_in, const int* in_sizes, int n_in,
                              void* d_out, int out_size) {
    const float* x   = (const float*)d_in[0];
    const void*  nbr = d_in[1];
    const float* ipw = (const float*)d_in[4];
    const float* ipb = (const float*)d_in[5];
    const float* opw = (const float*)d_in[6];
    const float* opb = (const float*)d_in[7];
    const float* cw  = (const float*)d_in[8];
    const float* cb  = (const float*)d_in[9];
    const int N = in_sizes[0] / 128;
    float* out = (float*)d_out;

    cudaFuncSetAttribute(mega_gemm, cudaFuncAttributeMaxDynamicSharedMemorySize, SMEM_BYTES);
    cudaFuncSetAttribute(out_gemm, cudaFuncAttributeMaxDynamicSharedMemorySize, SMEM_BYTES);

    const int tiles = (N + 127) / 128;

    detect_kernel<<<1, 32>>>((const int*)nbr);                 // 1
    prep_frag_mega<<<64, 256>>>(ipw, cw);                      // 2
    mega_gemm<<<tiles, 256, SMEM_BYTES>>>(x, ipb, N);          // 3
    attn_kernel<<<(N + 7) / 8, 256>>>(nbr, N);                 // 4  <- ncu slot
    prep_w2_kernel<<<128, 128>>>(cw, opw, opb, cb);            // 5
    prep_frag_w2<<<16, 256>>>();                               // 6
    out_gemm<<<tiles, 256, SMEM_BYTES>>>(x, out, N);           // 7
}